// round 2
// baseline (speedup 1.0000x reference)
#include <cuda_runtime.h>
#include <cstdint>

// ---- JAX PRNG variant: 1 = threefry_partitionable (modern JAX default), 0 = legacy ----
#define JAX_PARTITIONABLE 1

#define MAXP   (1024*2048)
#define NBMAX  ((MAXP/256)+1)
#define ITERS  1000
#define SUBN   50000

// ------------------ device scratch (static; no allocations) ------------------
__device__ int          g_n_valid;
__device__ int          g_bc[NBMAX];
__device__ int          g_idx[MAXP];
__device__ unsigned int g_pos[2*ITERS];
__device__ float        g_xsub[SUBN];
__device__ float        g_ysub[SUBN];
__device__ float        g_scales[ITERS];
__device__ float        g_shifts[ITERS];
__device__ int          g_counts[ITERS];
__device__ unsigned int g_hist[6][2048];
__device__ unsigned int g_sel_prefix;
__device__ long long    g_sel_rank;
__device__ unsigned int g_sel_key;
__device__ unsigned int g_sel_eq;
__device__ unsigned int g_minkey;
__device__ float        g_med;
__device__ float        g_dyn;
__device__ float        g_s;
__device__ float        g_t;
__device__ float        g_part[1024];

// ------------------ threefry2x32 (bit-exact vs JAX) ------------------
__host__ __device__ __forceinline__ void tf2x32(unsigned int k0, unsigned int k1,
                                                unsigned int x0, unsigned int x1,
                                                unsigned int& o0, unsigned int& o1) {
    unsigned int ks2 = k0 ^ k1 ^ 0x1BD11BDAu;
    x0 += k0; x1 += k1;
#define TF_RND(r) { x0 += x1; x1 = (x1 << (r)) | (x1 >> (32 - (r))); x1 ^= x0; }
    TF_RND(13) TF_RND(15) TF_RND(26) TF_RND(6)
    x0 += k1;  x1 += ks2 + 1u;
    TF_RND(17) TF_RND(29) TF_RND(16) TF_RND(24)
    x0 += ks2; x1 += k0 + 2u;
    TF_RND(13) TF_RND(15) TF_RND(26) TF_RND(6)
    x0 += k0;  x1 += k1 + 3u;
    TF_RND(17) TF_RND(29) TF_RND(16) TF_RND(24)
    x0 += k1;  x1 += ks2 + 4u;
    TF_RND(13) TF_RND(15) TF_RND(26) TF_RND(6)
    x0 += ks2; x1 += k0 + 5u;
#undef TF_RND
    o0 = x0; o1 = x1;
}

// random_bits(key, 32, n)[e]
__device__ __forceinline__ unsigned int jax_bits(unsigned int ka, unsigned int kb,
                                                 unsigned int e, unsigned int n) {
#if JAX_PARTITIONABLE
    unsigned int a, b;
    tf2x32(ka, kb, 0u, e, a, b);
    return a ^ b;
#else
    unsigned int h = n >> 1;
    unsigned int lane = (e < h) ? e : (e - h);
    unsigned int a, b;
    tf2x32(ka, kb, lane, lane + h, a, b);
    return (e < h) ? a : b;
#endif
}

// host-side split(key, 2): out[0..1]=k1, out[2..3]=k2
static inline void jax_split2_host(unsigned int ka, unsigned int kb, unsigned int* o) {
#if JAX_PARTITIONABLE
    unsigned int a, b;
    tf2x32(ka, kb, 0u, 0u, a, b); o[0] = a; o[1] = b;
    tf2x32(ka, kb, 0u, 1u, a, b); o[2] = a; o[3] = b;
#else
    unsigned int a0, b0, a1, b1;
    tf2x32(ka, kb, 0u, 2u, a0, b0);
    tf2x32(ka, kb, 1u, 3u, a1, b1);
    o[0] = a0; o[1] = a1; o[2] = b0; o[3] = b1;
#endif
}

__device__ __forceinline__ bool maskf(float d) {
    return (d > 0.1f) && (d < 100.0f) && isfinite(d);
}

// ------------------ kernels ------------------
__global__ void k_init() {
    int i = blockIdx.x * blockDim.x + threadIdx.x;
    if (i < 6 * 2048) ((unsigned int*)g_hist)[i] = 0u;
    if (i == 0) g_n_valid = 0;
}

__global__ void k_mask_y(const float* __restrict__ dren, float* __restrict__ yout, int P) {
    int acc = 0;
    for (int i = blockIdx.x * blockDim.x + threadIdx.x; i < P; i += gridDim.x * blockDim.x) {
        float d = dren[i];
        yout[i] = __fdiv_rn(1.0f, __fadd_rn(d, 1e-6f));
        acc += maskf(d) ? 1 : 0;
    }
    for (int o = 16; o; o >>= 1) acc += __shfl_down_sync(0xffffffffu, acc, o);
    __shared__ int wsum[8];
    if ((threadIdx.x & 31) == 0) wsum[threadIdx.x >> 5] = acc;
    __syncthreads();
    if (threadIdx.x == 0) {
        int s = 0;
        for (int w = 0; w < (int)(blockDim.x >> 5); w++) s += wsum[w];
        atomicAdd(&g_n_valid, s);
    }
}

__global__ void k_bcount(const float* __restrict__ dren, int P) {
    int i = blockIdx.x * blockDim.x + threadIdx.x;
    bool m = (i < P) && maskf(dren[i]);
    int cnt = __syncthreads_count(m ? 1 : 0);
    if (threadIdx.x == 0) g_bc[blockIdx.x] = cnt;
}

__global__ void k_scan(int nb) {
    __shared__ int sh[1024];
    int t = threadIdx.x;
    int per = (nb + 1023) >> 10;      // <= 16 for P <= 4M
    int local[16];
    int base = t * per;
    int s = 0;
    for (int j = 0; j < per; j++) {
        int v = (base + j < nb) ? g_bc[base + j] : 0;
        local[j] = s; s += v;
    }
    sh[t] = s; __syncthreads();
    for (int off = 1; off < 1024; off <<= 1) {
        int v = (t >= off) ? sh[t - off] : 0;
        __syncthreads();
        sh[t] += v;
        __syncthreads();
    }
    int excl = (t == 0) ? 0 : sh[t - 1];
    for (int j = 0; j < per; j++)
        if (base + j < nb) g_bc[base + j] = excl + local[j];
}

__global__ void k_scatter(const float* __restrict__ dren, int P) {
    int t = threadIdx.x;
    int i = blockIdx.x * blockDim.x + t;
    bool m = (i < P) && maskf(dren[i]);
    unsigned int bal = __ballot_sync(0xffffffffu, m);
    int lane = t & 31, w = t >> 5;
    int wpre = __popc(bal & ((1u << lane) - 1u));
    __shared__ int wtot[8], woff[8];
    if (lane == 0) wtot[w] = __popc(bal);
    __syncthreads();
    if (t == 0) {
        int s = 0;
        for (int j = 0; j < 8; j++) { woff[j] = s; s += wtot[j]; }
    }
    __syncthreads();
    if (m) g_idx[g_bc[blockIdx.x] + woff[w] + wpre] = i;
}

// randint offset per JAX _randint (uint32 wraparound semantics)
__device__ __forceinline__ unsigned int randint_off(unsigned int hb, unsigned int lb,
                                                    unsigned int span) {
    unsigned int m = 65536u % span;
    m = (m * m) % span;
    unsigned int off = (hb % span) * m + (lb % span);
    return off % span;
}

__global__ void k_sample_pairs(uint4 K) {
    int e = blockIdx.x * blockDim.x + threadIdx.x;
    if (e >= 2 * ITERS) return;
    unsigned int span = (unsigned int)g_n_valid;
    if (span == 0u) { g_pos[e] = 0u; return; }
    unsigned int hb = jax_bits(K.x, K.y, (unsigned int)e, 2u * ITERS);
    unsigned int lb = jax_bits(K.z, K.w, (unsigned int)e, 2u * ITERS);
    g_pos[e] = randint_off(hb, lb, span);
}

__global__ void k_hyp(const float* __restrict__ dpri, const float* __restrict__ y) {
    int i = blockIdx.x * blockDim.x + threadIdx.x;
    if (i >= ITERS) return;
    int i0 = g_idx[g_pos[2 * i]];
    int i1 = g_idx[g_pos[2 * i + 1]];
    float x1 = dpri[i0], x2 = dpri[i1];
    float y1 = y[i0],    y2 = y[i1];
    float sc = __fdiv_rn(__fsub_rn(y2, y1), __fadd_rn(__fsub_rn(x2, x1), 1e-8f));
    float sh = __fsub_rn(y1, __fmul_rn(sc, x1));
    g_scales[i] = sc;
    g_shifts[i] = sh;
    g_counts[i] = 0;
}

__global__ void k_sample_sub(uint4 K, const float* __restrict__ dpri,
                             const float* __restrict__ y) {
    int e = blockIdx.x * blockDim.x + threadIdx.x;
    if (e >= SUBN) return;
    unsigned int span = (unsigned int)g_n_valid;
    if (span == 0u) { g_xsub[e] = 0.f; g_ysub[e] = 0.f; return; }
    unsigned int hb = jax_bits(K.x, K.y, (unsigned int)e, SUBN);
    unsigned int lb = jax_bits(K.z, K.w, (unsigned int)e, SUBN);
    int si = g_idx[randint_off(hb, lb, span)];
    g_xsub[e] = dpri[si];
    g_ysub[e] = y[si];
}

// ---- histogram radix-select (exact nanmedian) ----
__global__ void k_selinit() {
    int n = g_n_valid;
    g_sel_rank = (n > 0) ? (long long)((n - 1) / 2) : 0ll;
    g_sel_prefix = 0u;
    g_minkey = 0xFFFFFFFFu;
}

__device__ __forceinline__ unsigned int sel_key_of(float yv, int stage, float med) {
    float v = (stage == 0) ? yv : fabsf(__fsub_rn(yv, med));
    return __float_as_uint(v);
}

__global__ void k_hist(const float* __restrict__ y, const float* __restrict__ dren,
                       int P, int level, int stage, int hi) {
    __shared__ unsigned int sh[2048];
    for (int j = threadIdx.x; j < 2048; j += blockDim.x) sh[j] = 0u;
    __syncthreads();
    float med = g_med;
    unsigned int prefix = g_sel_prefix;
    for (int i = blockIdx.x * blockDim.x + threadIdx.x; i < P; i += gridDim.x * blockDim.x) {
        float d = dren[i];
        if (!maskf(d)) continue;
        unsigned int key = sel_key_of(y[i], stage, med);
        if (level == 0) {
            atomicAdd(&sh[key >> 21], 1u);
        } else if (level == 1) {
            if ((key >> 21) == prefix) atomicAdd(&sh[(key >> 10) & 2047u], 1u);
        } else {
            if ((key >> 10) == prefix) atomicAdd(&sh[key & 1023u], 1u);
        }
    }
    __syncthreads();
    for (int j = threadIdx.x; j < 2048; j += blockDim.x)
        if (sh[j]) atomicAdd(&g_hist[hi][j], sh[j]);
}

__global__ void k_choose(int level, int hi) {
    if (threadIdx.x != 0 || blockIdx.x != 0) return;
    long long r = g_sel_rank;
    int nb = (level == 2) ? 1024 : 2048;
    long long c = 0;
    int b = 0;
    for (; b < nb - 1; b++) {
        long long h = (long long)g_hist[hi][b];
        if (c + h > r) break;
        c += h;
    }
    g_sel_rank = r - c;
    if (level == 0)       g_sel_prefix = (unsigned int)b;
    else if (level == 1)  g_sel_prefix = (g_sel_prefix << 11) | (unsigned int)b;
    else {
        g_sel_key = (g_sel_prefix << 10) | (unsigned int)b;
        g_sel_eq  = g_hist[hi][b];
    }
}

__global__ void k_min(const float* __restrict__ y, const float* __restrict__ dren,
                      int P, int stage) {
    float med = g_med;
    unsigned int kref = g_sel_key;
    unsigned int local = 0xFFFFFFFFu;
    for (int i = blockIdx.x * blockDim.x + threadIdx.x; i < P; i += gridDim.x * blockDim.x) {
        float d = dren[i];
        if (!maskf(d)) continue;
        unsigned int key = sel_key_of(y[i], stage, med);
        if (key > kref && key < local) local = key;
    }
    for (int o = 16; o; o >>= 1) {
        unsigned int v = __shfl_down_sync(0xffffffffu, local, o);
        if (v < local) local = v;
    }
    if ((threadIdx.x & 31) == 0) atomicMin(&g_minkey, local);
}

__global__ void k_fin(int stage) {
    int n = g_n_valid;
    float va = __uint_as_float(g_sel_key);
    float med;
    if (n & 1) {
        med = va;   // weight 0 -> low value
    } else {
        float vb = ((unsigned long long)(g_sel_rank + 1) < (unsigned long long)g_sel_eq)
                   ? va : __uint_as_float(g_minkey);
        med = __fadd_rn(__fmul_rn(va, 0.5f), __fmul_rn(vb, 0.5f));
    }
    if (stage == 0) {
        g_med = med;
    } else {
        float dyn = __fmul_rn(med, 0.5f);
        if (dyn < 1e-5f) dyn = 0.01f;
        g_dyn = dyn;
    }
}

// ---- RANSAC scoring: 4 hypotheses per block ----
__global__ void k_count() {
    int h0 = blockIdx.x * 4;
    float s[4], tt[4];
    int c[4] = {0, 0, 0, 0};
#pragma unroll
    for (int k = 0; k < 4; k++) {
        int h = h0 + k;
        s[k]  = (h < ITERS) ? g_scales[h] : 0.f;
        tt[k] = (h < ITERS) ? g_shifts[h] : 0.f;
    }
    float dyn = g_dyn;
    for (int j = threadIdx.x; j < SUBN; j += blockDim.x) {
        float x = g_xsub[j], yv = g_ysub[j];
#pragma unroll
        for (int k = 0; k < 4; k++) {
            float r = fabsf(__fsub_rn(__fadd_rn(__fmul_rn(s[k], x), tt[k]), yv));
            c[k] += (r < dyn) ? 1 : 0;
        }
    }
#pragma unroll
    for (int k = 0; k < 4; k++) {
        int v = c[k];
        for (int o = 16; o; o >>= 1) v += __shfl_down_sync(0xffffffffu, v, o);
        if ((threadIdx.x & 31) == 0 && (h0 + k) < ITERS) atomicAdd(&g_counts[h0 + k], v);
    }
}

__global__ void k_argmax() {
    __shared__ int sc[1024], si[1024];
    int t = threadIdx.x;
    int best = -2, bidx = 0x7FFFFFFF;
    for (int i = t; i < ITERS; i += 1024) {
        int c = (g_scales[i] > 0.0f) ? g_counts[i] : -1;
        if (c > best || (c == best && i < bidx)) { best = c; bidx = i; }
    }
    sc[t] = best; si[t] = bidx;
    __syncthreads();
    for (int off = 512; off; off >>= 1) {
        if (t < off) {
            if (sc[t + off] > sc[t] || (sc[t + off] == sc[t] && si[t + off] < si[t])) {
                sc[t] = sc[t + off]; si[t] = si[t + off];
            }
        }
        __syncthreads();
    }
    if (t == 0) {
        bool valid = sc[0] >= 0;
        float s  = valid ? g_scales[si[0]] : 1.0f;
        float tt = valid ? g_shifts[si[0]] : 0.0f;
        if (g_n_valid < 10) { s = 1.0f; tt = 0.0f; }
        g_s = s; g_t = tt;
    }
}

__global__ void k_out(const float* __restrict__ dren, const float* __restrict__ dpri,
                      const float* __restrict__ y, float* __restrict__ depth_out, int P) {
    float s = g_s, t = g_t;
    float acc = 0.f;
    for (int i = blockIdx.x * blockDim.x + threadIdx.x; i < P; i += gridDim.x * blockDim.x) {
        float al = __fadd_rn(__fmul_rn(s, dpri[i]), t);
        depth_out[i] = __fdiv_rn(1.0f, fmaxf(al, 1e-4f));
        if (maskf(dren[i])) acc += fabsf(__fsub_rn(al, y[i]));
    }
    __shared__ float sh[256];
    sh[threadIdx.x] = acc;
    __syncthreads();
    for (int off = 128; off; off >>= 1) {
        if (threadIdx.x < off) sh[threadIdx.x] += sh[threadIdx.x + off];
        __syncthreads();
    }
    if (threadIdx.x == 0) g_part[blockIdx.x] = sh[0];
}

__global__ void k_final(float* __restrict__ o) {
    if (threadIdx.x != 0 || blockIdx.x != 0) return;
    double acc = 0.0;
    for (int i = 0; i < 1024; i++) acc += (double)g_part[i];
    int n = g_n_valid;
    int denom = (n > 1) ? n : 1;
    float l1 = (float)acc / (float)denom;
    float loss = __fmul_rn(0.5f, l1);
    if (n < 100) loss = 0.0f;
    o[0] = loss;
}

// ------------------ launch ------------------
extern "C" void kernel_launch(void* const* d_in, const int* in_sizes, int n_in,
                              void* d_out, int out_size) {
    const float* dren = (const float*)d_in[0];
    const float* dpri = (const float*)d_in[1];
    float* o = (float*)d_out;
    int P = in_sizes[0];
    float* yout  = o + 1;
    float* dout2 = o + 1 + P;

    // derive threefry subkeys on host (constants; graph-capture safe)
    unsigned int kk[4], kp[4], ks[4];
    jax_split2_host(0u, 42u, kk);           // k_pair=(kk0,kk1), k_sub=(kk2,kk3)
    jax_split2_host(kk[0], kk[1], kp);      // randint-internal split of k_pair
    jax_split2_host(kk[2], kk[3], ks);      // randint-internal split of k_sub
    uint4 KP = make_uint4(kp[0], kp[1], kp[2], kp[3]);
    uint4 KS = make_uint4(ks[0], ks[1], ks[2], ks[3]);

    int nb = (P + 255) / 256;

    k_init<<<12, 1024>>>();
    k_mask_y<<<1024, 256>>>(dren, yout, P);
    k_bcount<<<nb, 256>>>(dren, P);
    k_scan<<<1, 1024>>>(nb);
    k_scatter<<<nb, 256>>>(dren, P);
    k_sample_pairs<<<2, 1024>>>(KP);
    k_hyp<<<1, 1024>>>(dpri, yout);
    k_sample_sub<<<(SUBN + 255) / 256, 256>>>(KS, dpri, yout);

    // stage 0: median of y
    k_selinit<<<1, 1>>>();
    k_hist<<<1024, 256>>>(yout, dren, P, 0, 0, 0); k_choose<<<1, 1>>>(0, 0);
    k_hist<<<1024, 256>>>(yout, dren, P, 1, 0, 1); k_choose<<<1, 1>>>(1, 1);
    k_hist<<<1024, 256>>>(yout, dren, P, 2, 0, 2); k_choose<<<1, 1>>>(2, 2);
    k_min<<<1024, 256>>>(yout, dren, P, 0);
    k_fin<<<1, 1>>>(0);

    // stage 1: median of |y - med|
    k_selinit<<<1, 1>>>();
    k_hist<<<1024, 256>>>(yout, dren, P, 0, 1, 3); k_choose<<<1, 1>>>(0, 3);
    k_hist<<<1024, 256>>>(yout, dren, P, 1, 1, 4); k_choose<<<1, 1>>>(1, 4);
    k_hist<<<1024, 256>>>(yout, dren, P, 2, 1, 5); k_choose<<<1, 1>>>(2, 5);
    k_min<<<1024, 256>>>(yout, dren, P, 1);
    k_fin<<<1, 1>>>(1);

    k_count<<<(ITERS + 3) / 4, 256>>>();
    k_argmax<<<1, 1024>>>();
    k_out<<<1024, 256>>>(dren, dpri, yout, dout2, P);
    k_final<<<1, 1>>>(o);
}

// round 4
// speedup vs baseline: 3.0654x; 3.0654x over previous
#include <cuda_runtime.h>
#include <cstdint>

#define JAX_PARTITIONABLE 1

#define MAXP   (1024*2048)
#define NBLK   1024
#define ITERS  1000
#define SUBN   50000

// ------------------ device scratch ------------------
__device__ int          g_n_valid;
__device__ int          g_bc[NBLK];
__device__ int          g_idx[MAXP];
__device__ float        g_xsub[SUBN];
__device__ float        g_ysub[SUBN];
__device__ float        g_scales[ITERS];
__device__ float        g_shifts[ITERS];
__device__ int          g_counts[ITERS];
__device__ unsigned int g_hist[6][2048];
__device__ unsigned int g_sel_prefix;
__device__ long long    g_sel_rank;
__device__ unsigned int g_sel_key;
__device__ unsigned int g_vbkey;
__device__ int          g_need_min;
__device__ unsigned int g_minkey;
__device__ float        g_med;
__device__ float        g_dyn;
__device__ float        g_s;
__device__ float        g_t;
__device__ float        g_part[1024];

// ------------------ threefry2x32 (bit-exact vs JAX) ------------------
__host__ __device__ __forceinline__ void tf2x32(unsigned int k0, unsigned int k1,
                                                unsigned int x0, unsigned int x1,
                                                unsigned int& o0, unsigned int& o1) {
    unsigned int ks2 = k0 ^ k1 ^ 0x1BD11BDAu;
    x0 += k0; x1 += k1;
#define TF_RND(r) { x0 += x1; x1 = (x1 << (r)) | (x1 >> (32 - (r))); x1 ^= x0; }
    TF_RND(13) TF_RND(15) TF_RND(26) TF_RND(6)
    x0 += k1;  x1 += ks2 + 1u;
    TF_RND(17) TF_RND(29) TF_RND(16) TF_RND(24)
    x0 += ks2; x1 += k0 + 2u;
    TF_RND(13) TF_RND(15) TF_RND(26) TF_RND(6)
    x0 += k0;  x1 += k1 + 3u;
    TF_RND(17) TF_RND(29) TF_RND(16) TF_RND(24)
    x0 += k1;  x1 += ks2 + 4u;
    TF_RND(13) TF_RND(15) TF_RND(26) TF_RND(6)
    x0 += ks2; x1 += k0 + 5u;
#undef TF_RND
    o0 = x0; o1 = x1;
}

__device__ __forceinline__ unsigned int jax_bits(unsigned int ka, unsigned int kb,
                                                 unsigned int e, unsigned int n) {
#if JAX_PARTITIONABLE
    unsigned int a, b;
    tf2x32(ka, kb, 0u, e, a, b);
    return a ^ b;
#else
    unsigned int h = n >> 1;
    unsigned int lane = (e < h) ? e : (e - h);
    unsigned int a, b;
    tf2x32(ka, kb, lane, lane + h, a, b);
    return (e < h) ? a : b;
#endif
}

static inline void jax_split2_host(unsigned int ka, unsigned int kb, unsigned int* o) {
#if JAX_PARTITIONABLE
    unsigned int a, b;
    tf2x32(ka, kb, 0u, 0u, a, b); o[0] = a; o[1] = b;
    tf2x32(ka, kb, 0u, 1u, a, b); o[2] = a; o[3] = b;
#else
    unsigned int a0, b0, a1, b1;
    tf2x32(ka, kb, 0u, 2u, a0, b0);
    tf2x32(ka, kb, 1u, 3u, a1, b1);
    o[0] = a0; o[1] = a1; o[2] = b0; o[3] = b1;
#endif
}

__device__ __forceinline__ bool maskf(float d) {
    return (d > 0.1f) && (d < 100.0f) && isfinite(d);
}

__device__ __forceinline__ float y_of(float d) {
    return __fdiv_rn(1.0f, __fadd_rn(d, 1e-6f));
}

__device__ __forceinline__ unsigned int randint_off(unsigned int hb, unsigned int lb,
                                                    unsigned int span) {
    unsigned int m = 65536u % span;
    m = (m * m) % span;
    unsigned int off = (hb % span) * m + (lb % span);
    return off % span;
}

// ------------------ kernels ------------------
__global__ void k_init() {
    int i = blockIdx.x * blockDim.x + threadIdx.x;
    if (i < 6 * 2048) ((unsigned int*)g_hist)[i] = 0u;
    if (i == 0) g_n_valid = 0;
}

// fused: y compute+store, per-chunk mask count, n_valid, stage0 level-0 hist
__global__ void k_fused1(const float* __restrict__ dren, float* __restrict__ yout,
                         int P, int chunk) {
    __shared__ unsigned int sh[2048];
    __shared__ int wsum[8];
    for (int j = threadIdx.x; j < 2048; j += 256) sh[j] = 0u;
    __syncthreads();
    int start = blockIdx.x * chunk;
    int end = min(start + chunk, P);
    int acc = 0;
    for (int i = start + threadIdx.x; i < end; i += 256) {
        float d = dren[i];
        float y = y_of(d);
        yout[i] = y;
        if (maskf(d)) {
            acc++;
            atomicAdd(&sh[__float_as_uint(y) >> 21], 1u);
        }
    }
    for (int o = 16; o; o >>= 1) acc += __shfl_down_sync(0xffffffffu, acc, o);
    if ((threadIdx.x & 31) == 0) wsum[threadIdx.x >> 5] = acc;
    __syncthreads();
    if (threadIdx.x == 0) {
        int s = 0;
        for (int w = 0; w < 8; w++) s += wsum[w];
        g_bc[blockIdx.x] = s;
        atomicAdd(&g_n_valid, s);
    }
    for (int j = threadIdx.x; j < 2048; j += 256)
        if (sh[j]) atomicAdd(&g_hist[0][j], sh[j]);
}

// parallel histogram-bin selection (block of 1024 threads)
__device__ __forceinline__ void choose_body(int level, int hi) {
    __shared__ unsigned int spre[1024];
    __shared__ int s_b;
    __shared__ long long s_e;
    __shared__ int s_next;
    int t = threadIdx.x;
    int nb = (level == 2) ? 1024 : 2048;
    unsigned int v0 = (2 * t < nb) ? g_hist[hi][2 * t] : 0u;
    unsigned int v1 = (2 * t + 1 < nb) ? g_hist[hi][2 * t + 1] : 0u;
    spre[t] = v0 + v1;
    if (t == 0) { s_b = -1; s_next = nb; }
    __syncthreads();
    for (int off = 1; off < 1024; off <<= 1) {
        unsigned int add = (t >= off) ? spre[t - off] : 0u;
        __syncthreads();
        spre[t] += add;
        __syncthreads();
    }
    long long r = g_sel_rank;
    long long total = (long long)spre[1023];
    long long E0 = (t ? (long long)spre[t - 1] : 0ll);
    long long E1 = E0 + (long long)v0;
    if (r >= E0 && r < E0 + (long long)v0) { s_b = 2 * t;     s_e = E0; }
    if (r >= E1 && r < E1 + (long long)v1) { s_b = 2 * t + 1; s_e = E1; }
    __syncthreads();
    int b = s_b;
    if (level == 2 && b >= 0) {
        if (2 * t > b && v0) atomicMin(&s_next, 2 * t);
        if (2 * t + 1 > b && v1) atomicMin(&s_next, 2 * t + 1);
    }
    __syncthreads();
    if (t == 0) {
        long long e = s_e;
        if (b < 0) { b = nb - 1; e = total; }  // degenerate (n==0); downstream clamped
        long long rl = r - e;
        g_sel_rank = rl;
        if (level == 0) g_sel_prefix = (unsigned int)b;
        else if (level == 1) g_sel_prefix = (g_sel_prefix << 11) | (unsigned int)b;
        else {
            unsigned int selkey = (g_sel_prefix << 10) | (unsigned int)b;
            g_sel_key = selkey;
            unsigned int eq = g_hist[hi][b];
            int n = g_n_valid;
            int need = 0;
            unsigned int vb = selkey;
            if (!(n & 1)) {
                if (rl + 1 < (long long)eq) vb = selkey;
                else if (rl + 1 < total && s_next < nb)
                    vb = (g_sel_prefix << 10) | (unsigned int)s_next;
                else need = 1;
            }
            g_vbkey = vb;
            g_need_min = need;
            g_minkey = 0xFFFFFFFFu;
        }
    }
}

__global__ void k_choose_par(int level, int hi) { choose_body(level, hi); }

// scan g_bc (1024 entries) + choose stage0 level0
__global__ void k_small1() {
    __shared__ int s[1024];
    int t = threadIdx.x;
    if (t == 0) {
        int n = g_n_valid;
        g_sel_rank = (n > 0) ? (long long)((n - 1) / 2) : 0ll;
        g_sel_prefix = 0u;
    }
    int v = g_bc[t];
    s[t] = v;
    __syncthreads();
    for (int off = 1; off < 1024; off <<= 1) {
        int add = (t >= off) ? s[t - off] : 0;
        __syncthreads();
        s[t] += add;
        __syncthreads();
    }
    g_bc[t] = s[t] - v;   // exclusive
    __syncthreads();
    choose_body(0, 0);
}

// fused: stable scatter of mask indices + stage0 level-1 hist
__global__ void k_fused2(const float* __restrict__ dren, int P, int chunk) {
    __shared__ unsigned int sh[2048];
    __shared__ int wtot[8];
    __shared__ int sbase;
    for (int j = threadIdx.x; j < 2048; j += 256) sh[j] = 0u;
    if (threadIdx.x == 0) sbase = g_bc[blockIdx.x];
    unsigned int prefix = g_sel_prefix;
    __syncthreads();
    int start = blockIdx.x * chunk;
    int end = min(start + chunk, P);
    int lane = threadIdx.x & 31, w = threadIdx.x >> 5;
    for (int it = start; it < end; it += 256) {
        int i = it + threadIdx.x;
        float d = 0.f;
        bool m = false;
        if (i < end) { d = dren[i]; m = maskf(d); }
        unsigned int bal = __ballot_sync(0xffffffffu, m);
        if (lane == 0) wtot[w] = __popc(bal);
        __syncthreads();
        int woff = 0;
        for (int j = 0; j < w; j++) woff += wtot[j];
        if (m) {
            g_idx[sbase + woff + __popc(bal & ((1u << lane) - 1u))] = i;
            unsigned int key = __float_as_uint(y_of(d));
            if ((key >> 21) == prefix) atomicAdd(&sh[(key >> 10) & 2047u], 1u);
        }
        __syncthreads();
        if (threadIdx.x == 0) {
            int stot = 0;
            for (int j = 0; j < 8; j++) stot += wtot[j];
            sbase += stot;
        }
        __syncthreads();
    }
    for (int j = threadIdx.x; j < 2048; j += 256)
        if (sh[j]) atomicAdd(&g_hist[1][j], sh[j]);
}

// generic hist pass (recomputes y from dren)
__global__ void k_hist(const float* __restrict__ dren, int P,
                       int level, int stage, int hi) {
    __shared__ unsigned int sh[2048];
    int nb = (level == 2) ? 1024 : 2048;
    for (int j = threadIdx.x; j < nb; j += blockDim.x) sh[j] = 0u;
    __syncthreads();
    float med = g_med;
    unsigned int prefix = g_sel_prefix;
    for (int i = blockIdx.x * blockDim.x + threadIdx.x; i < P; i += gridDim.x * blockDim.x) {
        float d = dren[i];
        if (!maskf(d)) continue;
        float y = y_of(d);
        float v = stage ? fabsf(__fsub_rn(y, med)) : y;
        unsigned int key = __float_as_uint(v);
        if (level == 0) atomicAdd(&sh[key >> 21], 1u);
        else if (level == 1) { if ((key >> 21) == prefix) atomicAdd(&sh[(key >> 10) & 2047u], 1u); }
        else               { if ((key >> 10) == prefix) atomicAdd(&sh[key & 1023u], 1u); }
    }
    __syncthreads();
    for (int j = threadIdx.x; j < nb; j += blockDim.x)
        if (sh[j]) atomicAdd(&g_hist[hi][j], sh[j]);
}

// gated fallback: min key strictly greater than selected
__global__ void k_min(const float* __restrict__ dren, int P, int stage) {
    if (!g_need_min) return;
    float med = g_med;
    unsigned int kref = g_sel_key;
    unsigned int local = 0xFFFFFFFFu;
    for (int i = blockIdx.x * blockDim.x + threadIdx.x; i < P; i += gridDim.x * blockDim.x) {
        float d = dren[i];
        if (!maskf(d)) continue;
        float y = y_of(d);
        float v = stage ? fabsf(__fsub_rn(y, med)) : y;
        unsigned int key = __float_as_uint(v);
        if (key > kref && key < local) local = key;
    }
    for (int o = 16; o; o >>= 1) {
        unsigned int v = __shfl_down_sync(0xffffffffu, local, o);
        if (v < local) local = v;
    }
    if ((threadIdx.x & 31) == 0) atomicMin(&g_minkey, local);
}

__global__ void k_fin(int stage) {
    if (threadIdx.x != 0 || blockIdx.x != 0) return;
    int n = g_n_valid;
    float va = __uint_as_float(g_sel_key);
    float med;
    if (n & 1) med = va;
    else {
        float vb = g_need_min ? __uint_as_float(g_minkey) : __uint_as_float(g_vbkey);
        med = __fadd_rn(__fmul_rn(va, 0.5f), __fmul_rn(vb, 0.5f));
    }
    if (stage == 0) {
        g_med = med;
        g_sel_rank = (n > 0) ? (long long)((n - 1) / 2) : 0ll;
        g_sel_prefix = 0u;
    } else {
        float dyn = __fmul_rn(med, 0.5f);
        if (dyn < 1e-5f) dyn = 0.01f;
        g_dyn = dyn;
    }
}

// fused sampling: pairs+hypotheses (e<1000) and subsample (e<50000)
__global__ void k_sampleall(uint4 KP, uint4 KS,
                            const float* __restrict__ dpri,
                            const float* __restrict__ y) {
    int e = blockIdx.x * blockDim.x + threadIdx.x;
    unsigned int span = (unsigned int)g_n_valid;
    if (e < SUBN) {
        if (span == 0u) { g_xsub[e] = 0.f; g_ysub[e] = 0.f; }
        else {
            unsigned int hb = jax_bits(KS.x, KS.y, (unsigned int)e, SUBN);
            unsigned int lb = jax_bits(KS.z, KS.w, (unsigned int)e, SUBN);
            int si = g_idx[randint_off(hb, lb, span)];
            g_xsub[e] = dpri[si];
            g_ysub[e] = y[si];
        }
    }
    if (e < ITERS) {
        g_counts[e] = 0;
        unsigned int p0 = 0u, p1 = 0u;
        if (span != 0u) {
            p0 = randint_off(jax_bits(KP.x, KP.y, 2u * e, 2u * ITERS),
                             jax_bits(KP.z, KP.w, 2u * e, 2u * ITERS), span);
            p1 = randint_off(jax_bits(KP.x, KP.y, 2u * e + 1u, 2u * ITERS),
                             jax_bits(KP.z, KP.w, 2u * e + 1u, 2u * ITERS), span);
        }
        int i0 = g_idx[p0];
        int i1 = g_idx[p1];
        float x1 = dpri[i0], x2 = dpri[i1];
        float y1 = y[i0],    y2 = y[i1];
        float sc = __fdiv_rn(__fsub_rn(y2, y1), __fadd_rn(__fsub_rn(x2, x1), 1e-8f));
        g_scales[e] = sc;
        g_shifts[e] = __fsub_rn(y1, __fmul_rn(sc, x1));
    }
}

// RANSAC scoring: 4 hypotheses per block
__global__ void k_count() {
    int h0 = blockIdx.x * 4;
    float s[4], tt[4];
    int c[4] = {0, 0, 0, 0};
#pragma unroll
    for (int k = 0; k < 4; k++) {
        int h = h0 + k;
        s[k]  = (h < ITERS) ? g_scales[h] : 0.f;
        tt[k] = (h < ITERS) ? g_shifts[h] : 0.f;
    }
    float dyn = g_dyn;
    for (int j = threadIdx.x; j < SUBN; j += blockDim.x) {
        float x = g_xsub[j], yv = g_ysub[j];
#pragma unroll
        for (int k = 0; k < 4; k++) {
            float r = fabsf(__fsub_rn(__fadd_rn(__fmul_rn(s[k], x), tt[k]), yv));
            c[k] += (r < dyn) ? 1 : 0;
        }
    }
#pragma unroll
    for (int k = 0; k < 4; k++) {
        int v = c[k];
        for (int o = 16; o; o >>= 1) v += __shfl_down_sync(0xffffffffu, v, o);
        if ((threadIdx.x & 31) == 0 && (h0 + k) < ITERS) atomicAdd(&g_counts[h0 + k], v);
    }
}

__global__ void k_argmax() {
    __shared__ int sc[1024], si[1024];
    int t = threadIdx.x;
    int best = -2, bidx = 0x7FFFFFFF;
    for (int i = t; i < ITERS; i += 1024) {
        int c = (g_scales[i] > 0.0f) ? g_counts[i] : -1;
        if (c > best || (c == best && i < bidx)) { best = c; bidx = i; }
    }
    sc[t] = best; si[t] = bidx;
    __syncthreads();
    for (int off = 512; off; off >>= 1) {
        if (t < off) {
            if (sc[t + off] > sc[t] || (sc[t + off] == sc[t] && si[t + off] < si[t])) {
                sc[t] = sc[t + off]; si[t] = si[t + off];
            }
        }
        __syncthreads();
    }
    if (t == 0) {
        bool valid = sc[0] >= 0;
        float s  = valid ? g_scales[si[0]] : 1.0f;
        float tt = valid ? g_shifts[si[0]] : 0.0f;
        if (g_n_valid < 10) { s = 1.0f; tt = 0.0f; }
        g_s = s; g_t = tt;
    }
}

__global__ void k_out(const float* __restrict__ dren, const float* __restrict__ dpri,
                      float* __restrict__ depth_out, int P) {
    float s = g_s, t = g_t;
    float acc = 0.f;
    for (int i = blockIdx.x * blockDim.x + threadIdx.x; i < P; i += gridDim.x * blockDim.x) {
        float d = dren[i];
        float al = __fadd_rn(__fmul_rn(s, dpri[i]), t);
        depth_out[i] = __fdiv_rn(1.0f, fmaxf(al, 1e-4f));
        if (maskf(d)) acc += fabsf(__fsub_rn(al, y_of(d)));
    }
    __shared__ float sh[256];
    sh[threadIdx.x] = acc;
    __syncthreads();
    for (int off = 128; off; off >>= 1) {
        if (threadIdx.x < off) sh[threadIdx.x] += sh[threadIdx.x + off];
        __syncthreads();
    }
    if (threadIdx.x == 0) g_part[blockIdx.x] = sh[0];
}

__global__ void k_final(float* __restrict__ o) {
    __shared__ double sh[1024];
    int t = threadIdx.x;
    sh[t] = (double)g_part[t];
    __syncthreads();
    for (int off = 512; off; off >>= 1) {
        if (t < off) sh[t] += sh[t + off];
        __syncthreads();
    }
    if (t == 0) {
        int n = g_n_valid;
        int denom = (n > 1) ? n : 1;
        float l1 = (float)sh[0] / (float)denom;
        float loss = __fmul_rn(0.5f, l1);
        if (n < 100) loss = 0.0f;
        o[0] = loss;
    }
}

// ------------------ launch ------------------
extern "C" void kernel_launch(void* const* d_in, const int* in_sizes, int n_in,
                              void* d_out, int out_size) {
    const float* dren = (const float*)d_in[0];
    const float* dpri = (const float*)d_in[1];
    float* o = (float*)d_out;
    int P = in_sizes[0];
    float* yout  = o + 1;
    float* dout2 = o + 1 + P;

    unsigned int kk[4], kp[4], ks[4];
    jax_split2_host(0u, 42u, kk);
    jax_split2_host(kk[0], kk[1], kp);
    jax_split2_host(kk[2], kk[3], ks);
    uint4 KP = make_uint4(kp[0], kp[1], kp[2], kp[3]);
    uint4 KS = make_uint4(ks[0], ks[1], ks[2], ks[3]);

    int chunk = (P + NBLK - 1) / NBLK;

    k_init<<<12, 1024>>>();
    k_fused1<<<NBLK, 256>>>(dren, yout, P, chunk);
    k_small1<<<1, 1024>>>();                      // scan g_bc + choose s0 L0
    k_fused2<<<NBLK, 256>>>(dren, P, chunk);      // scatter + hist s0 L1
    k_choose_par<<<1, 1024>>>(1, 1);
    k_sampleall<<<(SUBN + 255) / 256, 256>>>(KP, KS, dpri, yout);
    k_hist<<<1024, 256>>>(dren, P, 2, 0, 2);
    k_choose_par<<<1, 1024>>>(2, 2);
    k_min<<<256, 256>>>(dren, P, 0);
    k_fin<<<1, 1>>>(0);
    k_hist<<<1024, 256>>>(dren, P, 0, 1, 3);
    k_choose_par<<<1, 1024>>>(0, 3);
    k_hist<<<1024, 256>>>(dren, P, 1, 1, 4);
    k_choose_par<<<1, 1024>>>(1, 4);
    k_hist<<<1024, 256>>>(dren, P, 2, 1, 5);
    k_choose_par<<<1, 1024>>>(2, 5);
    k_min<<<256, 256>>>(dren, P, 1);
    k_fin<<<1, 1>>>(1);
    k_count<<<(ITERS + 3) / 4, 256>>>();
    k_argmax<<<1, 1024>>>();
    k_out<<<1024, 256>>>(dren, dpri, dout2, P);
    k_final<<<1, 1024>>>(o);
}

// round 7
// speedup vs baseline: 4.0820x; 1.3316x over previous
#include <cuda_runtime.h>
#include <cstdint>

#define JAX_PARTITIONABLE 1

#define MAXP   (1024*2048)
#define NBMAX  1024
#define ITERS  1000
#define SUBN   50000
#define HB     256      // grid for hist/sample kernels
#define OUTB   1024     // grid for k_out
#define CNTB   1000     // grid for k_count (8 hyps x 1/8 subsample per block)

// ------------------ device scratch ------------------
__device__ int          g_n_valid;
__device__ int          g_bc[NBMAX];
__device__ int          g_idx[MAXP];
__device__ float        g_xsub[SUBN];
__device__ float        g_ysub[SUBN];
__device__ float        g_scales[ITERS];
__device__ float        g_shifts[ITERS];
__device__ int          g_counts[ITERS];
__device__ unsigned int g_hist[6][2048];
__device__ unsigned int g_done[8];
__device__ unsigned int g_sel_prefix;
__device__ long long    g_sel_rank;
__device__ float        g_med;
__device__ float        g_dyn;
__device__ float        g_s;
__device__ float        g_t;
__device__ float        g_part[OUTB];

// ------------------ threefry2x32 (bit-exact vs JAX) ------------------
__host__ __device__ __forceinline__ void tf2x32(unsigned int k0, unsigned int k1,
                                                unsigned int x0, unsigned int x1,
                                                unsigned int& o0, unsigned int& o1) {
    unsigned int ks2 = k0 ^ k1 ^ 0x1BD11BDAu;
    x0 += k0; x1 += k1;
#define TF_RND(r) { x0 += x1; x1 = (x1 << (r)) | (x1 >> (32 - (r))); x1 ^= x0; }
    TF_RND(13) TF_RND(15) TF_RND(26) TF_RND(6)
    x0 += k1;  x1 += ks2 + 1u;
    TF_RND(17) TF_RND(29) TF_RND(16) TF_RND(24)
    x0 += ks2; x1 += k0 + 2u;
    TF_RND(13) TF_RND(15) TF_RND(26) TF_RND(6)
    x0 += k0;  x1 += k1 + 3u;
    TF_RND(17) TF_RND(29) TF_RND(16) TF_RND(24)
    x0 += k1;  x1 += ks2 + 4u;
    TF_RND(13) TF_RND(15) TF_RND(26) TF_RND(6)
    x0 += ks2; x1 += k0 + 5u;
#undef TF_RND
    o0 = x0; o1 = x1;
}

__device__ __forceinline__ unsigned int jax_bits(unsigned int ka, unsigned int kb,
                                                 unsigned int e, unsigned int n) {
#if JAX_PARTITIONABLE
    unsigned int a, b;
    tf2x32(ka, kb, 0u, e, a, b);
    return a ^ b;
#else
    unsigned int h = n >> 1;
    unsigned int lane = (e < h) ? e : (e - h);
    unsigned int a, b;
    tf2x32(ka, kb, lane, lane + h, a, b);
    return (e < h) ? a : b;
#endif
}

static inline void jax_split2_host(unsigned int ka, unsigned int kb, unsigned int* o) {
#if JAX_PARTITIONABLE
    unsigned int a, b;
    tf2x32(ka, kb, 0u, 0u, a, b); o[0] = a; o[1] = b;
    tf2x32(ka, kb, 0u, 1u, a, b); o[2] = a; o[3] = b;
#else
    unsigned int a0, b0, a1, b1;
    tf2x32(ka, kb, 0u, 2u, a0, b0);
    tf2x32(ka, kb, 1u, 3u, a1, b1);
    o[0] = a0; o[1] = a1; o[2] = b0; o[3] = b1;
#endif
}

__device__ __forceinline__ bool maskf(float d) {
    return (d > 0.1f) && (d < 100.0f) && isfinite(d);
}
__device__ __forceinline__ float y_of(float d) {
    return __fdiv_rn(1.0f, __fadd_rn(d, 1e-6f));
}
__device__ __forceinline__ unsigned int randint_off(unsigned int hb, unsigned int lb,
                                                    unsigned int span) {
    unsigned int m = 65536u % span;
    m = (m * m) % span;
    unsigned int off = (hb % span) * m + (lb % span);
    return off % span;
}

// exclusive scan over 256 threads via warp shuffles; wsh = shared int[8]
__device__ __forceinline__ int blk_scan256(int v, int* wsh) {
    int t = threadIdx.x, lane = t & 31, w = t >> 5;
    int incl = v;
#pragma unroll
    for (int off = 1; off < 32; off <<= 1) {
        int x = __shfl_up_sync(0xffffffffu, incl, off);
        if (lane >= off) incl += x;
    }
    if (lane == 31) wsh[w] = incl;
    __syncthreads();
    if (w == 0) {
        int s = (lane < 8) ? wsh[lane] : 0;
#pragma unroll
        for (int off = 1; off < 8; off <<= 1) {
            int x = __shfl_up_sync(0xffffffffu, s, off);
            if (lane >= off) s += x;
        }
        if (lane < 8) wsh[lane] = s;   // inclusive warp prefix
    }
    __syncthreads();
    return (w ? wsh[w - 1] : 0) + incl - v;
}

// last-block election
__device__ __forceinline__ bool is_last_block(int id, unsigned int grid) {
    __threadfence();
    __shared__ unsigned int s_last;
    if (threadIdx.x == 0)
        s_last = (atomicAdd(&g_done[id], 1u) == grid - 1u) ? 1u : 0u;
    __syncthreads();
    return s_last != 0u;
}

// parallel bin selection over g_hist[hi]; levels 0/1: 2048 bins, level 2: 1024.
// Level 2 finalizes the median (inline rare full-scan fallback for rank-at-bin-edge).
__device__ void choose_level(int level, int stage, int hi,
                             const float* __restrict__ dren, int P) {
    __shared__ int wsh[8];
    __shared__ int sh_b;
    __shared__ long long sh_e;
    __shared__ int sh_next;
    __shared__ unsigned int sh_tot;
    __shared__ int sh_need;
    __shared__ unsigned int sh_selkey, sh_vb;
    __shared__ unsigned int red[256];

    int t = threadIdx.x;
    int nb = (level == 2) ? 1024 : 2048;
    int per = nb >> 8;
    unsigned int v[8];
    int sum = 0;
#pragma unroll
    for (int j = 0; j < 8; j++) {
        v[j] = (j < per) ? g_hist[hi][t * per + j] : 0u;
        sum += (int)v[j];
    }
    if (t == 0) { sh_b = -1; sh_next = nb; }
    __syncthreads();
    int excl = blk_scan256(sum, wsh);
    if (t == 255) sh_tot = (unsigned int)(excl + sum);
    __syncthreads();
    long long r = g_sel_rank;
    if (r >= (long long)excl && r < (long long)(excl + sum)) {
        long long c = excl;
        for (int j = 0; j < per; j++) {
            if (r < c + (long long)v[j]) { sh_b = t * per + j; sh_e = c; break; }
            c += (long long)v[j];
        }
    }
    __syncthreads();
    int b = sh_b;
    if (level == 2 && b >= 0) {
        for (int j = 0; j < per; j++) {
            int idx = t * per + j;
            if (idx > b && v[j]) { atomicMin(&sh_next, idx); break; }
        }
    }
    __syncthreads();
    if (t == 0) {
        long long e = sh_e;
        int bb = b;
        long long tot = (long long)sh_tot;
        if (bb < 0) { bb = nb - 1; e = tot; }   // degenerate n==0
        long long rl = r - e;
        g_sel_rank = rl;
        if (level == 0) g_sel_prefix = (unsigned int)bb;
        else if (level == 1) g_sel_prefix = (g_sel_prefix << 11) | (unsigned int)bb;
        else {
            unsigned int selkey = (g_sel_prefix << 10) | (unsigned int)bb;
            unsigned int eq = g_hist[hi][bb];
            int n = g_n_valid;
            int need = 0;
            unsigned int vb = selkey;
            if (!(n & 1)) {
                if (rl + 1 < (long long)eq) vb = selkey;
                else if (sh_next < nb)
                    vb = (g_sel_prefix << 10) | (unsigned int)sh_next;
                else need = 1;
            }
            sh_need = need; sh_selkey = selkey; sh_vb = vb;
        }
    }
    __syncthreads();
    if (level != 2) return;

    unsigned int selkey = sh_selkey;
    unsigned int vb;
    if (sh_need) {
        // rare fallback: full scan for min key strictly greater than selkey
        float med = g_med;
        unsigned int local = 0xFFFFFFFFu;
        for (int i = t; i < P; i += 256) {
            float d = dren[i];
            if (!maskf(d)) continue;
            float y = y_of(d);
            float vv = stage ? fabsf(__fsub_rn(y, med)) : y;
            unsigned int key = __float_as_uint(vv);
            if (key > selkey && key < local) local = key;
        }
        red[t] = local;
        __syncthreads();
        for (int off = 128; off; off >>= 1) {
            if (t < off) red[t] = min(red[t], red[t + off]);
            __syncthreads();
        }
        vb = red[0];
    } else vb = sh_vb;

    if (t == 0) {
        int n = g_n_valid;
        float va = __uint_as_float(selkey);
        float med = (n & 1) ? va
            : __fadd_rn(__fmul_rn(va, 0.5f), __fmul_rn(__uint_as_float(vb), 0.5f));
        if (stage == 0) {
            g_med = med;
            g_sel_rank = (n > 0) ? (long long)((n - 1) / 2) : 0ll;
            g_sel_prefix = 0u;
        } else {
            float dyn = __fmul_rn(med, 0.5f);
            if (dyn < 1e-5f) dyn = 0.01f;
            g_dyn = dyn;
        }
    }
}

// ------------------ kernels ------------------
__global__ void k_init() {
    int i = blockIdx.x * blockDim.x + threadIdx.x;
    if (i < 6 * 2048) ((unsigned int*)g_hist)[i] = 0u;
    if (i < 8) g_done[i] = 0u;
    if (i < ITERS) g_counts[i] = 0;
}

// y compute+store, per-block valid count, stage0 L0 hist;
// last block: scan g_bc, set n_valid/rank, choose L0s0
__global__ void __launch_bounds__(256)
k_fused1(const float* __restrict__ dren, float* __restrict__ yout, int P, int NB) {
    __shared__ unsigned int sh[2048];
    __shared__ int wsh[8];
    __shared__ int sh_tot;
    int t = threadIdx.x;
    for (int j = t; j < 2048; j += 256) sh[j] = 0u;
    __syncthreads();
    int s0 = blockIdx.x * 2048 + t * 8;
    int cnt = 0;
    if (s0 + 8 <= P) {
        float4 a = *(const float4*)(dren + s0);
        float4 b = *(const float4*)(dren + s0 + 4);
        float dd[8] = {a.x, a.y, a.z, a.w, b.x, b.y, b.z, b.w};
#pragma unroll
        for (int k = 0; k < 8; k++) {
            float y = y_of(dd[k]);
            yout[s0 + k] = y;
            if (maskf(dd[k])) { cnt++; atomicAdd(&sh[__float_as_uint(y) >> 21], 1u); }
        }
    } else {
        for (int i = s0; i < P && i < s0 + 8; i++) {
            float d = dren[i];
            float y = y_of(d);
            yout[i] = y;
            if (maskf(d)) { cnt++; atomicAdd(&sh[__float_as_uint(y) >> 21], 1u); }
        }
    }
    // block total -> g_bc
    int lane = t & 31, w = t >> 5;
    int v = cnt;
    for (int o = 16; o; o >>= 1) v += __shfl_down_sync(0xffffffffu, v, o);
    if (lane == 0) wsh[w] = v;
    __syncthreads();
    if (t == 0) {
        int s = 0;
        for (int j = 0; j < 8; j++) s += wsh[j];
        g_bc[blockIdx.x] = s;
    }
    __syncthreads();
    for (int j = t; j < 2048; j += 256)
        if (sh[j]) atomicAdd(&g_hist[0][j], sh[j]);

    if (!is_last_block(0, gridDim.x)) return;

    // scan g_bc (NB entries, <=1024), 4 per thread
    int b4[4]; int s = 0;
#pragma unroll
    for (int j = 0; j < 4; j++) {
        int ii = t * 4 + j;
        b4[j] = (ii < NB) ? g_bc[ii] : 0;
        s += b4[j];
    }
    int ex = blk_scan256(s, wsh);
    int run = ex;
#pragma unroll
    for (int j = 0; j < 4; j++) {
        int ii = t * 4 + j;
        if (ii < NB) g_bc[ii] = run;
        run += b4[j];
    }
    if (t == 255) sh_tot = ex + s;
    __syncthreads();
    if (t == 0) {
        int n = sh_tot;
        g_n_valid = n;
        g_sel_rank = (n > 0) ? (long long)((n - 1) / 2) : 0ll;
        g_sel_prefix = 0u;
    }
    __syncthreads();
    choose_level(0, 0, 0, dren, P);
}

// stable index scatter + stage0 L1 hist; last block: choose L1s0
__global__ void __launch_bounds__(256)
k_fused2(const float* __restrict__ dren, int P) {
    __shared__ unsigned int sh[2048];
    __shared__ int wsh[8];
    int t = threadIdx.x;
    for (int j = t; j < 2048; j += 256) sh[j] = 0u;
    unsigned int prefix = g_sel_prefix;
    __syncthreads();
    int s0 = blockIdx.x * 2048 + t * 8;
    int cnt = 0;
    unsigned int bits = 0u;
    if (s0 + 8 <= P) {
        float4 a = *(const float4*)(dren + s0);
        float4 b = *(const float4*)(dren + s0 + 4);
        float dd[8] = {a.x, a.y, a.z, a.w, b.x, b.y, b.z, b.w};
#pragma unroll
        for (int k = 0; k < 8; k++) {
            if (maskf(dd[k])) {
                cnt++; bits |= (1u << k);
                unsigned int key = __float_as_uint(y_of(dd[k]));
                if ((key >> 21) == prefix) atomicAdd(&sh[(key >> 10) & 2047u], 1u);
            }
        }
    } else {
        for (int i = s0; i < P && i < s0 + 8; i++) {
            float d = dren[i];
            if (maskf(d)) {
                cnt++; bits |= (1u << (i - s0));
                unsigned int key = __float_as_uint(y_of(d));
                if ((key >> 21) == prefix) atomicAdd(&sh[(key >> 10) & 2047u], 1u);
            }
        }
    }
    int excl = blk_scan256(cnt, wsh);
    int wpos = g_bc[blockIdx.x] + excl;
#pragma unroll
    for (int k = 0; k < 8; k++)
        if ((bits >> k) & 1u) g_idx[wpos++] = s0 + k;
    __syncthreads();
    for (int j = t; j < 2048; j += 256)
        if (sh[j]) atomicAdd(&g_hist[1][j], sh[j]);

    if (!is_last_block(1, gridDim.x)) return;
    choose_level(1, 0, 1, dren, P);
}

// stage0 L2 hist + RANSAC sampling (pairs/hyps + subsample); LB: choose L2s0 + med
__global__ void __launch_bounds__(256)
k_h20s(const float* __restrict__ dren, const float* __restrict__ dpri,
       const float* __restrict__ yout, int P, uint4 KP, uint4 KS) {
    __shared__ unsigned int sh[1024];
    int t = threadIdx.x;
    int gid = blockIdx.x * 256 + t;
    for (int j = t; j < 1024; j += 256) sh[j] = 0u;
    unsigned int prefix = g_sel_prefix;
    unsigned int span = (unsigned int)g_n_valid;
    __syncthreads();

    int P4 = P >> 2;
    const float4* dren4 = (const float4*)dren;
    for (int q = gid; q < P4; q += HB * 256) {
        float4 a = dren4[q];
        float dd[4] = {a.x, a.y, a.z, a.w};
#pragma unroll
        for (int k = 0; k < 4; k++) {
            if (maskf(dd[k])) {
                unsigned int key = __float_as_uint(y_of(dd[k]));
                if ((key >> 10) == prefix) atomicAdd(&sh[key & 1023u], 1u);
            }
        }
    }
    for (int i = P4 * 4 + gid; i < P; i += HB * 256) {
        float d = dren[i];
        if (maskf(d)) {
            unsigned int key = __float_as_uint(y_of(d));
            if ((key >> 10) == prefix) atomicAdd(&sh[key & 1023u], 1u);
        }
    }

    // sampling work (subsample + hypotheses)
    if (gid < SUBN) {
        if (span == 0u) { g_xsub[gid] = 0.f; g_ysub[gid] = 0.f; }
        else {
            unsigned int hb = jax_bits(KS.x, KS.y, (unsigned int)gid, SUBN);
            unsigned int lb = jax_bits(KS.z, KS.w, (unsigned int)gid, SUBN);
            int si = g_idx[randint_off(hb, lb, span)];
            g_xsub[gid] = dpri[si];
            g_ysub[gid] = yout[si];
        }
    }
    if (gid < ITERS) {
        unsigned int p0 = 0u, p1 = 0u;
        if (span != 0u) {
            p0 = randint_off(jax_bits(KP.x, KP.y, 2u * gid, 2u * ITERS),
                             jax_bits(KP.z, KP.w, 2u * gid, 2u * ITERS), span);
            p1 = randint_off(jax_bits(KP.x, KP.y, 2u * gid + 1u, 2u * ITERS),
                             jax_bits(KP.z, KP.w, 2u * gid + 1u, 2u * ITERS), span);
        }
        int i0 = g_idx[p0];
        int i1 = g_idx[p1];
        float x1 = dpri[i0], x2 = dpri[i1];
        float y1 = yout[i0], y2 = yout[i1];
        float sc = __fdiv_rn(__fsub_rn(y2, y1), __fadd_rn(__fsub_rn(x2, x1), 1e-8f));
        g_scales[gid] = sc;
        g_shifts[gid] = __fsub_rn(y1, __fmul_rn(sc, x1));
    }
    __syncthreads();
    for (int j = t; j < 1024; j += 256)
        if (sh[j]) atomicAdd(&g_hist[2][j], sh[j]);

    if (!is_last_block(2, gridDim.x)) return;
    choose_level(2, 0, 2, dren, P);
}

// generic stage1 hist pass; LB: choose (level 2 also finalizes g_dyn)
__global__ void __launch_bounds__(256)
k_hist1(const float* __restrict__ dren, int P, int level, int hi, int doneid) {
    __shared__ unsigned int sh[2048];
    int t = threadIdx.x;
    int nb = (level == 2) ? 1024 : 2048;
    for (int j = t; j < nb; j += 256) sh[j] = 0u;
    float med = g_med;
    unsigned int prefix = g_sel_prefix;
    __syncthreads();
    int gid = blockIdx.x * 256 + t;
    int P4 = P >> 2;
    const float4* dren4 = (const float4*)dren;
    for (int q = gid; q < P4; q += HB * 256) {
        float4 a = dren4[q];
        float dd[4] = {a.x, a.y, a.z, a.w};
#pragma unroll
        for (int k = 0; k < 4; k++) {
            if (!maskf(dd[k])) continue;
            float vv = fabsf(__fsub_rn(y_of(dd[k]), med));
            unsigned int key = __float_as_uint(vv);
            if (level == 0) atomicAdd(&sh[key >> 21], 1u);
            else if (level == 1) { if ((key >> 21) == prefix) atomicAdd(&sh[(key >> 10) & 2047u], 1u); }
            else { if ((key >> 10) == prefix) atomicAdd(&sh[key & 1023u], 1u); }
        }
    }
    for (int i = P4 * 4 + gid; i < P; i += HB * 256) {
        float d = dren[i];
        if (!maskf(d)) continue;
        float vv = fabsf(__fsub_rn(y_of(d), med));
        unsigned int key = __float_as_uint(vv);
        if (level == 0) atomicAdd(&sh[key >> 21], 1u);
        else if (level == 1) { if ((key >> 21) == prefix) atomicAdd(&sh[(key >> 10) & 2047u], 1u); }
        else { if ((key >> 10) == prefix) atomicAdd(&sh[key & 1023u], 1u); }
    }
    __syncthreads();
    for (int j = t; j < nb; j += 256)
        if (sh[j]) atomicAdd(&g_hist[hi][j], sh[j]);

    if (!is_last_block(doneid, gridDim.x)) return;
    choose_level(level, 1, hi, dren, P);
}

// RANSAC scoring: block b -> hyps [8*(b%125),+8) x subsample segment b/125
// LB: argmax -> g_s, g_t
__global__ void __launch_bounds__(256)
k_count() {
    __shared__ int wc[8][8];
    __shared__ int sc[256], si[256];
    int t = threadIdx.x;
    int hy = (blockIdx.x % 125) * 8;
    int seg = blockIdx.x / 125;
    int j0 = seg * (SUBN / 8), j1 = j0 + (SUBN / 8);
    float s[8], tv[8];
    int c[8] = {0, 0, 0, 0, 0, 0, 0, 0};
#pragma unroll
    for (int k = 0; k < 8; k++) { s[k] = g_scales[hy + k]; tv[k] = g_shifts[hy + k]; }
    float dyn = g_dyn;
    for (int j = j0 + t; j < j1; j += 256) {
        float x = g_xsub[j], yv = g_ysub[j];
#pragma unroll
        for (int k = 0; k < 8; k++) {
            float r = fabsf(__fsub_rn(__fadd_rn(__fmul_rn(s[k], x), tv[k]), yv));
            c[k] += (r < dyn) ? 1 : 0;
        }
    }
    int lane = t & 31, w = t >> 5;
#pragma unroll
    for (int k = 0; k < 8; k++) {
        int v = c[k];
        for (int o = 16; o; o >>= 1) v += __shfl_down_sync(0xffffffffu, v, o);
        if (lane == 0) wc[w][k] = v;
    }
    __syncthreads();
    if (t < 8) {
        int v = 0;
        for (int j = 0; j < 8; j++) v += wc[j][t];
        atomicAdd(&g_counts[hy + t], v);
    }

    if (!is_last_block(6, gridDim.x)) return;

    int best = -2, bidx = 0x7FFFFFFF;
    for (int i = t; i < ITERS; i += 256) {
        int cc = (g_scales[i] > 0.0f) ? g_counts[i] : -1;
        if (cc > best || (cc == best && i < bidx)) { best = cc; bidx = i; }
    }
    sc[t] = best; si[t] = bidx;
    __syncthreads();
    for (int off = 128; off; off >>= 1) {
        if (t < off) {
            if (sc[t + off] > sc[t] || (sc[t + off] == sc[t] && si[t + off] < si[t])) {
                sc[t] = sc[t + off]; si[t] = si[t + off];
            }
        }
        __syncthreads();
    }
    if (t == 0) {
        bool valid = sc[0] >= 0;
        float ss = valid ? g_scales[si[0]] : 1.0f;
        float tt = valid ? g_shifts[si[0]] : 0.0f;
        if (g_n_valid < 10) { ss = 1.0f; tt = 0.0f; }
        g_s = ss; g_t = tt;
    }
}

// outputs + loss partials; LB: final loss
__global__ void __launch_bounds__(256)
k_out(const float* __restrict__ dren, const float* __restrict__ dpri,
      float* __restrict__ depth_out, float* __restrict__ o, int P) {
    __shared__ float shf[256];
    __shared__ double shd[256];
    int t = threadIdx.x;
    int gid = blockIdx.x * 256 + t;
    float s = g_s, tt = g_t;
    float acc = 0.f;
    int P4 = P >> 2;
    const float4* dren4 = (const float4*)dren;
    const float4* dpri4 = (const float4*)dpri;
    for (int q = gid; q < P4; q += OUTB * 256) {
        float4 a = dren4[q];
        float4 p = dpri4[q];
        float dd[4] = {a.x, a.y, a.z, a.w};
        float pp[4] = {p.x, p.y, p.z, p.w};
#pragma unroll
        for (int k = 0; k < 4; k++) {
            float al = __fadd_rn(__fmul_rn(s, pp[k]), tt);
            depth_out[4 * q + k] = __fdiv_rn(1.0f, fmaxf(al, 1e-4f));
            if (maskf(dd[k])) acc += fabsf(__fsub_rn(al, y_of(dd[k])));
        }
    }
    for (int i = P4 * 4 + gid; i < P; i += OUTB * 256) {
        float al = __fadd_rn(__fmul_rn(s, dpri[i]), tt);
        depth_out[i] = __fdiv_rn(1.0f, fmaxf(al, 1e-4f));
        if (maskf(dren[i])) acc += fabsf(__fsub_rn(al, y_of(dren[i])));
    }
    shf[t] = acc;
    __syncthreads();
    for (int off = 128; off; off >>= 1) {
        if (t < off) shf[t] += shf[t + off];
        __syncthreads();
    }
    if (t == 0) g_part[blockIdx.x] = shf[0];

    if (!is_last_block(7, gridDim.x)) return;

    double d = 0.0;
    for (int i = t; i < OUTB; i += 256) d += (double)g_part[i];
    shd[t] = d;
    __syncthreads();
    for (int off = 128; off; off >>= 1) {
        if (t < off) shd[t] += shd[t + off];
        __syncthreads();
    }
    if (t == 0) {
        int n = g_n_valid;
        int denom = (n > 1) ? n : 1;
        float l1 = (float)shd[0] / (float)denom;
        float loss = __fmul_rn(0.5f, l1);
        if (n < 100) loss = 0.0f;
        o[0] = loss;
    }
}

// ------------------ launch ------------------
extern "C" void kernel_launch(void* const* d_in, const int* in_sizes, int n_in,
                              void* d_out, int out_size) {
    const float* dren = (const float*)d_in[0];
    const float* dpri = (const float*)d_in[1];
    float* o = (float*)d_out;
    int P = in_sizes[0];
    float* yout  = o + 1;
    float* dout2 = o + 1 + P;

    unsigned int kk[4], kp[4], ks[4];
    jax_split2_host(0u, 42u, kk);
    jax_split2_host(kk[0], kk[1], kp);
    jax_split2_host(kk[2], kk[3], ks);
    uint4 KP = make_uint4(kp[0], kp[1], kp[2], kp[3]);
    uint4 KS = make_uint4(ks[0], ks[1], ks[2], ks[3]);

    int NB = (P + 2047) / 2048;   // blocks of 256 threads x 8 elems

    k_init<<<16, 1024>>>();
    k_fused1<<<NB, 256>>>(dren, yout, P, NB);
    k_fused2<<<NB, 256>>>(dren, P);
    k_h20s<<<HB, 256>>>(dren, dpri, yout, P, KP, KS);
    k_hist1<<<HB, 256>>>(dren, P, 0, 3, 3);
    k_hist1<<<HB, 256>>>(dren, P, 1, 4, 4);
    k_hist1<<<HB, 256>>>(dren, P, 2, 5, 5);
    k_count<<<CNTB, 256>>>();
    k_out<<<OUTB, 256>>>(dren, dpri, dout2, o, P);
}